// round 1
// baseline (speedup 1.0000x reference)
#include <cuda_runtime.h>
#include <math.h>

#define NB 2
#define NL 5000
#define HW 256
#define NPIX 65536
#define CIN 256
#define CL 128
#define PL 64
#define EPSB 1e-5f

// ---------------- device scratch (no allocations allowed) ----------------
__device__ float g_xbuf[(size_t)NB * NPIX * CL];   // fc1 output, [b][h][w][c]  (64 MB)
__device__ float g_fc1t[CIN * CL];                 // fc1_w transposed [c][o]
__device__ float g_a1[CL], g_b1c[CL];              // BN1 fold
__device__ float g_w1t[CL * PL], g_b1f[PL];        // conv1 (BN2 folded), [c][o]
__device__ float g_w2t[PL * 3 * PL], g_b2f[PL];    // conv2 (BN3 folded), [i][k][o]
__device__ float g_w3t[PL * CL];                   // conv3 transposed [i][o]

// ---------------- prep: fold BN, transpose weights ----------------
__global__ void prep_kernel(const float* __restrict__ fc1_w,
                            const float* __restrict__ bn1_g, const float* __restrict__ bn1_b,
                            const float* __restrict__ bn1_m, const float* __restrict__ bn1_v,
                            const float* __restrict__ conv1_w, const float* __restrict__ conv1_b,
                            const float* __restrict__ bn2_g, const float* __restrict__ bn2_b,
                            const float* __restrict__ bn2_m, const float* __restrict__ bn2_v,
                            const float* __restrict__ conv2_w, const float* __restrict__ conv2_b,
                            const float* __restrict__ bn3_g, const float* __restrict__ bn3_b,
                            const float* __restrict__ bn3_m, const float* __restrict__ bn3_v,
                            const float* __restrict__ conv3_w) {
    __shared__ float a2s[PL], a3s[PL];
    int tid = threadIdx.x;
    if (tid < CL) {
        float a = bn1_g[tid] * rsqrtf(bn1_v[tid] + EPSB);
        g_a1[tid]  = a;
        g_b1c[tid] = bn1_b[tid] - bn1_m[tid] * a;
    }
    if (tid < PL) {
        float a2 = bn2_g[tid] * rsqrtf(bn2_v[tid] + EPSB);
        a2s[tid] = a2;
        g_b1f[tid] = conv1_b[tid] * a2 + bn2_b[tid] - bn2_m[tid] * a2;
        float a3 = bn3_g[tid] * rsqrtf(bn3_v[tid] + EPSB);
        a3s[tid] = a3;
        g_b2f[tid] = conv2_b[tid] * a3 + bn3_b[tid] - bn3_m[tid] * a3;
    }
    __syncthreads();
    for (int i = tid; i < CL * PL; i += blockDim.x) {
        int c = i / PL, o = i % PL;
        g_w1t[i] = conv1_w[o * CL + c] * a2s[o];
    }
    for (int i = tid; i < PL * 3 * PL; i += blockDim.x) {
        int o = i % PL, ik = i / PL;
        int k = ik % 3, ii = ik / 3;
        g_w2t[i] = conv2_w[(o * PL + ii) * 3 + k] * a3s[o];
    }
    for (int i = tid; i < PL * CL; i += blockDim.x) {
        int o = i % CL, ii = i / CL;
        g_w3t[i] = conv3_w[o * PL + ii];
    }
    for (int i = tid; i < CIN * CL; i += blockDim.x) {
        int o = i % CL, c = i / CL;
        g_fc1t[i] = fc1_w[o * CIN + c];
    }
}

// ---------------- fc1: W[128,256] @ F[256, 131072] -> xbuf pixel-major ----------------
// CTA: 256 threads, tile = 128 o x 32 pixels, BK = 8.
// Thread (lo = tid&31, lp = tid>>5): 4 o x 4 px accumulators via float4 smem reads.
__global__ void fc1_kernel(const float* __restrict__ feature, const float* __restrict__ fc1_b) {
    __shared__ float Wt[8 * 128];  // [k][o]
    __shared__ float Ft[8 * 32];   // [k][px]
    int tid = threadIdx.x;
    int lo  = tid & 31;   // o-group (o0 = lo*4)
    int lp  = tid >> 5;   // px-group (px0 = lp*4)
    long p0 = (long)blockIdx.x * 32;
    int b    = (int)(p0 >> 16);
    int pix0 = (int)(p0 & 65535);
    const float* fb = feature + (size_t)b * CIN * NPIX;

    float acc[4][4] = {};
    int kload = tid >> 5;   // 0..7
    int eload = tid & 31;

    for (int c0 = 0; c0 < CIN; c0 += 8) {
        ((float4*)Wt)[tid] = ((const float4*)g_fc1t)[(size_t)(c0 + kload) * 32 + eload];
        Ft[tid] = fb[(size_t)(c0 + kload) * NPIX + pix0 + eload];
        __syncthreads();
#pragma unroll
        for (int k = 0; k < 8; k++) {
            float4 w = ((const float4*)Wt)[k * 32 + lo];
            float4 f = ((const float4*)Ft)[k * 8 + lp];
            acc[0][0] += f.x * w.x; acc[0][1] += f.x * w.y; acc[0][2] += f.x * w.z; acc[0][3] += f.x * w.w;
            acc[1][0] += f.y * w.x; acc[1][1] += f.y * w.y; acc[1][2] += f.y * w.z; acc[1][3] += f.y * w.w;
            acc[2][0] += f.z * w.x; acc[2][1] += f.z * w.y; acc[2][2] += f.z * w.z; acc[2][3] += f.z * w.w;
            acc[3][0] += f.w * w.x; acc[3][1] += f.w * w.y; acc[3][2] += f.w * w.z; acc[3][3] += f.w * w.w;
        }
        __syncthreads();
    }

    float4 bias = ((const float4*)fc1_b)[lo];
#pragma unroll
    for (int pi = 0; pi < 4; pi++) {
        int pix = pix0 + lp * 4 + pi;
        float4 r;
        r.x = acc[pi][0] + bias.x;
        r.y = acc[pi][1] + bias.y;
        r.z = acc[pi][2] + bias.z;
        r.w = acc[pi][3] + bias.w;
        ((float4*)g_xbuf)[((size_t)b * NPIX + pix) * 32 + lo] = r;
    }
}

// ---------------- per-line fused kernel ----------------
// 1 CTA (128 threads) per line. thread == channel for sampling / conv3 / fc2.
__global__ void line_kernel(const float* __restrict__ lines,
                            const float* __restrict__ conv3_b,
                            const float* __restrict__ fc2_w,
                            const float* __restrict__ fc2_b,
                            float* __restrict__ out) {
    __shared__ int   s_off[4][32];
    __shared__ float s_w[4][32];
    __shared__ float h0s[CL][8];
    __shared__ float h1s[PL][12];   // zero-padded: data at [o][1..8]
    __shared__ float h2s[PL][8];
    __shared__ float red[4][3];

    int tid = threadIdx.x;
    int n = blockIdx.x;
    int b = n / NL;

    if (tid < 32) {
        int p = tid;
        float lam = (float)p * (1.0f / 31.0f);
        const float* lp = lines + (size_t)n * 4;
        float px = lp[0] * lam + lp[2] * (1.0f - lam) - 0.5f;
        float py = lp[1] * lam + lp[3] * (1.0f - lam) - 0.5f;
        float px0 = fminf(fmaxf(floorf(px), 0.0f), 255.0f);
        float py0 = fminf(fmaxf(floorf(py), 0.0f), 255.0f);
        float px1 = fminf(px0 + 1.0f, 255.0f);
        float py1 = fminf(py0 + 1.0f, 255.0f);
        int ix0 = (int)px0, iy0 = (int)py0, ix1 = (int)px1, iy1 = (int)py1;
        s_off[0][p] = (ix0 * HW + iy0) * CL;
        s_off[1][p] = (ix1 * HW + iy0) * CL;
        s_off[2][p] = (ix0 * HW + iy1) * CL;
        s_off[3][p] = (ix1 * HW + iy1) * CL;
        s_w[0][p] = (px1 - px) * (py1 - py);
        s_w[1][p] = (px - px0) * (py1 - py);
        s_w[2][p] = (px1 - px) * (py - py0);
        s_w[3][p] = (px - px0) * (py - py0);
    }
    // zero conv2 padding rows
    for (int i = tid; i < PL * 12; i += 128) ((float*)h1s)[i] = 0.0f;
    __syncthreads();

    // ---- bilinear sample + maxpool(4) : thread = channel ----
    const float* xb = g_xbuf + (size_t)b * NPIX * CL + tid;
    float mx[8];
#pragma unroll
    for (int p = 0; p < 32; p++) {
        float v = s_w[0][p] * __ldg(xb + s_off[0][p])
                + s_w[1][p] * __ldg(xb + s_off[1][p])
                + s_w[2][p] * __ldg(xb + s_off[2][p])
                + s_w[3][p] * __ldg(xb + s_off[3][p]);
        int g = p >> 2;
        if ((p & 3) == 0) mx[g] = v; else mx[g] = fmaxf(mx[g], v);
    }

    // ---- BN1 + ReLU ----
    {
        float a1 = g_a1[tid], b1 = g_b1c[tid];
#pragma unroll
        for (int t = 0; t < 8; t++) h0s[tid][t] = fmaxf(mx[t] * a1 + b1, 0.0f);
    }
    __syncthreads();

    int o  = tid & 63;
    int th = tid >> 6;    // 0/1
    int t0 = th * 4;

    // ---- conv1 (1x1, 128->64) + BN2 + ReLU ----
    {
        float a[4] = {0.f, 0.f, 0.f, 0.f};
#pragma unroll 8
        for (int c = 0; c < CL; c++) {
            float4 h = *(const float4*)&h0s[c][t0];
            float w = __ldg(&g_w1t[c * PL + o]);
            a[0] += w * h.x; a[1] += w * h.y; a[2] += w * h.z; a[3] += w * h.w;
        }
        float bb = g_b1f[o];
#pragma unroll
        for (int j = 0; j < 4; j++) h1s[o][1 + t0 + j] = fmaxf(a[j] + bb, 0.0f);
    }
    __syncthreads();

    // ---- conv2 (k=3 pad=1, 64->64) + BN3 + ReLU ----
    {
        float a[4] = {0.f, 0.f, 0.f, 0.f};
#pragma unroll 8
        for (int i = 0; i < PL; i++) {
            float4 hv  = *(const float4*)&h1s[i][t0];
            float2 hv2 = *(const float2*)&h1s[i][t0 + 4];
            float w0 = __ldg(&g_w2t[(i * 3 + 0) * PL + o]);
            float w1 = __ldg(&g_w2t[(i * 3 + 1) * PL + o]);
            float w2 = __ldg(&g_w2t[(i * 3 + 2) * PL + o]);
            a[0] += w0 * hv.x + w1 * hv.y  + w2 * hv.z;
            a[1] += w0 * hv.y + w1 * hv.z  + w2 * hv.w;
            a[2] += w0 * hv.z + w1 * hv.w  + w2 * hv2.x;
            a[3] += w0 * hv.w + w1 * hv2.x + w2 * hv2.y;
        }
        float bb = g_b2f[o];
#pragma unroll
        for (int j = 0; j < 4; j++) h2s[o][t0 + j] = fmaxf(a[j] + bb, 0.0f);
    }
    __syncthreads();

    // ---- conv3 (1x1, 64->128) + residual + ReLU : thread = out channel ----
    float y[8];
    {
        float a[8] = {0.f, 0.f, 0.f, 0.f, 0.f, 0.f, 0.f, 0.f};
#pragma unroll 8
        for (int i = 0; i < PL; i++) {
            float4 hlo = *(const float4*)&h2s[i][0];
            float4 hhi = *(const float4*)&h2s[i][4];
            float w = __ldg(&g_w3t[i * CL + tid]);
            a[0] += w * hlo.x; a[1] += w * hlo.y; a[2] += w * hlo.z; a[3] += w * hlo.w;
            a[4] += w * hhi.x; a[5] += w * hhi.y; a[6] += w * hhi.z; a[7] += w * hhi.w;
        }
        float cb = __ldg(&conv3_b[tid]);
#pragma unroll
        for (int t = 0; t < 8; t++) y[t] = fmaxf(mx[t] + a[t] + cb, 0.0f);
    }

    // ---- fc2: [10000,1024] @ [1024,3]^T ----
    float s[3];
    const float4* fw = (const float4*)fc2_w;
#pragma unroll
    for (int k = 0; k < 3; k++) {
        float4 wa = __ldg(&fw[k * 256 + tid * 2]);
        float4 wb = __ldg(&fw[k * 256 + tid * 2 + 1]);
        s[k] = y[0] * wa.x + y[1] * wa.y + y[2] * wa.z + y[3] * wa.w
             + y[4] * wb.x + y[5] * wb.y + y[6] * wb.z + y[7] * wb.w;
    }
#pragma unroll
    for (int k = 0; k < 3; k++) {
#pragma unroll
        for (int off = 16; off > 0; off >>= 1)
            s[k] += __shfl_down_sync(0xffffffffu, s[k], off);
    }
    int wid = tid >> 5, lane = tid & 31;
    if (lane == 0) { red[wid][0] = s[0]; red[wid][1] = s[1]; red[wid][2] = s[2]; }
    __syncthreads();
    if (tid < 3) {
        out[(size_t)n * 3 + tid] = red[0][tid] + red[1][tid] + red[2][tid] + red[3][tid]
                                 + __ldg(&fc2_b[tid]);
    }
}

// ---------------- launch ----------------
extern "C" void kernel_launch(void* const* d_in, const int* in_sizes, int n_in,
                              void* d_out, int out_size) {
    const float* feature = (const float*)d_in[0];
    const float* lines   = (const float*)d_in[1];
    const float* fc1_w   = (const float*)d_in[2];
    const float* fc1_b   = (const float*)d_in[3];
    const float* bn1_g   = (const float*)d_in[4];
    const float* bn1_b   = (const float*)d_in[5];
    const float* bn1_m   = (const float*)d_in[6];
    const float* bn1_v   = (const float*)d_in[7];
    const float* conv1_w = (const float*)d_in[8];
    const float* conv1_b = (const float*)d_in[9];
    const float* bn2_g   = (const float*)d_in[10];
    const float* bn2_b   = (const float*)d_in[11];
    const float* bn2_m   = (const float*)d_in[12];
    const float* bn2_v   = (const float*)d_in[13];
    const float* conv2_w = (const float*)d_in[14];
    const float* conv2_b = (const float*)d_in[15];
    const float* bn3_g   = (const float*)d_in[16];
    const float* bn3_b   = (const float*)d_in[17];
    const float* bn3_m   = (const float*)d_in[18];
    const float* bn3_v   = (const float*)d_in[19];
    const float* conv3_w = (const float*)d_in[20];
    const float* conv3_b = (const float*)d_in[21];
    const float* fc2_w   = (const float*)d_in[22];
    const float* fc2_b   = (const float*)d_in[23];
    float* out = (float*)d_out;

    prep_kernel<<<1, 256>>>(fc1_w, bn1_g, bn1_b, bn1_m, bn1_v,
                            conv1_w, conv1_b, bn2_g, bn2_b, bn2_m, bn2_v,
                            conv2_w, conv2_b, bn3_g, bn3_b, bn3_m, bn3_v,
                            conv3_w);
    fc1_kernel<<<(NB * NPIX) / 32, 256>>>(feature, fc1_b);
    line_kernel<<<NB * NL, 128>>>(lines, conv3_b, fc2_w, fc2_b, out);
}

// round 2
// speedup vs baseline: 1.3516x; 1.3516x over previous
#include <cuda_runtime.h>
#include <math.h>
#include <stdint.h>

#define NB 2
#define NL 5000
#define HW 256
#define NPIX 65536
#define CIN 256
#define CL 128
#define PL 64
#define EPSB 1e-5f
#define TFMASK 0xFFFFE000u

// ---------------- device scratch (no allocations allowed) ----------------
__device__ float g_xbuf[(size_t)NB * NPIX * CL];   // fc1 output, [b][h][w][c]  (64 MB)
__device__ float g_fc1t[CIN * CL];                 // fc1_w transposed [c][o]
__device__ float g_a1[CL], g_b1c[CL];              // BN1 fold
__device__ float g_w1t[CL * PL], g_b1f[PL];        // conv1 (BN2 folded), [c][o]
__device__ float g_w2t[PL * 3 * PL], g_b2f[PL];    // conv2 (BN3 folded), [i][k][o]
__device__ float g_w3t[PL * CL];                   // conv3 transposed [i][o]

// ---------------- prep: fold BN, transpose weights (grid-stride) ----------------
__global__ void prep_kernel(const float* __restrict__ fc1_w,
                            const float* __restrict__ bn1_g, const float* __restrict__ bn1_b,
                            const float* __restrict__ bn1_m, const float* __restrict__ bn1_v,
                            const float* __restrict__ conv1_w, const float* __restrict__ conv1_b,
                            const float* __restrict__ bn2_g, const float* __restrict__ bn2_b,
                            const float* __restrict__ bn2_m, const float* __restrict__ bn2_v,
                            const float* __restrict__ conv2_w, const float* __restrict__ conv2_b,
                            const float* __restrict__ bn3_g, const float* __restrict__ bn3_b,
                            const float* __restrict__ bn3_m, const float* __restrict__ bn3_v,
                            const float* __restrict__ conv3_w) {
    int tid = blockIdx.x * blockDim.x + threadIdx.x;
    int nt = gridDim.x * blockDim.x;
    for (int i = tid; i < CL; i += nt) {
        float a = bn1_g[i] * rsqrtf(bn1_v[i] + EPSB);
        g_a1[i]  = a;
        g_b1c[i] = bn1_b[i] - bn1_m[i] * a;
    }
    for (int i = tid; i < PL; i += nt) {
        float a2 = bn2_g[i] * rsqrtf(bn2_v[i] + EPSB);
        g_b1f[i] = conv1_b[i] * a2 + bn2_b[i] - bn2_m[i] * a2;
        float a3 = bn3_g[i] * rsqrtf(bn3_v[i] + EPSB);
        g_b2f[i] = conv2_b[i] * a3 + bn3_b[i] - bn3_m[i] * a3;
    }
    for (int i = tid; i < CL * PL; i += nt) {
        int c = i / PL, o = i % PL;
        float a2 = bn2_g[o] * rsqrtf(bn2_v[o] + EPSB);
        g_w1t[i] = conv1_w[o * CL + c] * a2;
    }
    for (int i = tid; i < PL * 3 * PL; i += nt) {
        int o = i % PL, ik = i / PL;
        int k = ik % 3, ii = ik / 3;
        float a3 = bn3_g[o] * rsqrtf(bn3_v[o] + EPSB);
        g_w2t[i] = conv2_w[(o * PL + ii) * 3 + k] * a3;
    }
    for (int i = tid; i < PL * CL; i += nt) {
        int o = i % CL, ii = i / CL;
        g_w3t[i] = conv3_w[o * PL + ii];
    }
    for (int i = tid; i < CIN * CL; i += nt) {
        int o = i % CL, c = i / CL;
        g_fc1t[i] = fc1_w[o * CIN + c];
    }
}

// ---------------- fc1 via mma.sync tf32, 3-term fp32-split ----------------
// C[px, o] = F[px, c] * W[c, o]; output pixel-major xbuf[b][pix][o].
// CTA: 256 threads (8 warps, 2(m) x 4(n)). Tile M=128 px, N=128 o, K chunked by 32.
__device__ __forceinline__ void mma_tf32(float* d, uint32_t a0, uint32_t a1,
                                         uint32_t a2, uint32_t a3,
                                         uint32_t b0, uint32_t b1) {
    asm volatile(
        "mma.sync.aligned.m16n8k8.row.col.f32.tf32.tf32.f32 "
        "{%0,%1,%2,%3}, {%4,%5,%6,%7}, {%8,%9}, {%0,%1,%2,%3};\n"
        : "+f"(d[0]), "+f"(d[1]), "+f"(d[2]), "+f"(d[3])
        : "r"(a0), "r"(a1), "r"(a2), "r"(a3), "r"(b0), "r"(b1));
}

__global__ __launch_bounds__(256) void fc1_tc_kernel(const float* __restrict__ feature,
                                                     const float* __restrict__ fc1_b) {
    __shared__ float As[32][136];   // [c][px], pad 136 -> conflict-free frags
    __shared__ float Bs[32][136];   // [c][o]
    __shared__ float biass[128];

    int tid = threadIdx.x;
    long p0l = (long)blockIdx.x * 128;
    int b = (int)(p0l >> 16);
    int pix0 = (int)(p0l & 65535);
    const float* fb = feature + (size_t)b * CIN * NPIX + pix0;

    if (tid < 128) biass[tid] = fc1_b[tid];

    int wid = tid >> 5, lane = tid & 31;
    int warp_m = wid >> 2, warp_n = wid & 3;
    int grp = lane >> 2, qid = lane & 3;
    int pxb = warp_m * 64;
    int ob  = warp_n * 32;

    float acc[4][4][4];
#pragma unroll
    for (int mt = 0; mt < 4; mt++)
#pragma unroll
        for (int nt = 0; nt < 4; nt++)
#pragma unroll
            for (int j = 0; j < 4; j++) acc[mt][nt][j] = 0.0f;

    int lrow = tid >> 5;            // rows loaded by this thread: lrow (+8 per j step? no)
    int lc4  = tid & 31;

    // prefetch chunk 0
    float4 fa[4], fw[4];
#pragma unroll
    for (int j = 0; j < 4; j++) {
        int row = lrow + j * 8;     // (tid + 256*j) >> 5 = lrow + 8j
        fa[j] = *(const float4*)(fb + (size_t)row * NPIX + lc4 * 4);
        fw[j] = *(const float4*)(g_fc1t + row * CL + lc4 * 4);
    }

    for (int ch = 0; ch < 8; ch++) {
        __syncthreads();
#pragma unroll
        for (int j = 0; j < 4; j++) {
            int row = lrow + j * 8;
            *(float4*)&As[row][lc4 * 4] = fa[j];
            *(float4*)&Bs[row][lc4 * 4] = fw[j];
        }
        __syncthreads();
        if (ch < 7) {
            int c0 = (ch + 1) * 32;
#pragma unroll
            for (int j = 0; j < 4; j++) {
                int row = c0 + lrow + j * 8;
                fa[j] = *(const float4*)(fb + (size_t)row * NPIX + lc4 * 4);
                fw[j] = *(const float4*)(g_fc1t + row * CL + lc4 * 4);
            }
        }

#pragma unroll
        for (int ks = 0; ks < 4; ks++) {
            int kk = ks * 8;
            uint32_t ahi[4][4], alo[4][4];
#pragma unroll
            for (int mt = 0; mt < 4; mt++) {
                int px = pxb + mt * 16 + grp;
                float v0 = As[kk + qid][px];
                float v1 = As[kk + qid][px + 8];
                float v2 = As[kk + qid + 4][px];
                float v3 = As[kk + qid + 4][px + 8];
                // PTX A-frag order: a0=(r,c) a1=(r+8,c) a2=(r,c+4) a3=(r+8,c+4)
                uint32_t h0 = __float_as_uint(v0) & TFMASK;
                uint32_t h1 = __float_as_uint(v1) & TFMASK;
                uint32_t h2 = __float_as_uint(v2) & TFMASK;
                uint32_t h3 = __float_as_uint(v3) & TFMASK;
                ahi[mt][0] = h0; ahi[mt][1] = h1; ahi[mt][2] = h2; ahi[mt][3] = h3;
                alo[mt][0] = __float_as_uint(v0 - __uint_as_float(h0));
                alo[mt][1] = __float_as_uint(v1 - __uint_as_float(h1));
                alo[mt][2] = __float_as_uint(v2 - __uint_as_float(h2));
                alo[mt][3] = __float_as_uint(v3 - __uint_as_float(h3));
            }
#pragma unroll
            for (int nt = 0; nt < 4; nt++) {
                int oo = ob + nt * 8 + grp;
                float w0 = Bs[kk + qid][oo];
                float w1 = Bs[kk + qid + 4][oo];
                uint32_t bh0 = __float_as_uint(w0) & TFMASK;
                uint32_t bh1 = __float_as_uint(w1) & TFMASK;
                uint32_t bl0 = __float_as_uint(w0 - __uint_as_float(bh0));
                uint32_t bl1 = __float_as_uint(w1 - __uint_as_float(bh1));
#pragma unroll
                for (int mt = 0; mt < 4; mt++) {
                    mma_tf32(acc[mt][nt], ahi[mt][0], ahi[mt][1], ahi[mt][2], ahi[mt][3], bh0, bh1);
                    mma_tf32(acc[mt][nt], ahi[mt][0], ahi[mt][1], ahi[mt][2], ahi[mt][3], bl0, bl1);
                    mma_tf32(acc[mt][nt], alo[mt][0], alo[mt][1], alo[mt][2], alo[mt][3], bh0, bh1);
                }
            }
        }
    }

    // store: c0=(r,2q) c1=(r,2q+1) c2=(r+8,2q) c3=(r+8,2q+1)
#pragma unroll
    for (int mt = 0; mt < 4; mt++) {
#pragma unroll
        for (int nt = 0; nt < 4; nt++) {
            int px = pix0 + pxb + mt * 16 + grp;
            int oo = ob + nt * 8 + qid * 2;
            float bx = biass[oo], by = biass[oo + 1];
            float2 r0 = make_float2(acc[mt][nt][0] + bx, acc[mt][nt][1] + by);
            float2 r1 = make_float2(acc[mt][nt][2] + bx, acc[mt][nt][3] + by);
            size_t base = ((size_t)b * NPIX + px) * CL + oo;
            *(float2*)&g_xbuf[base] = r0;
            *(float2*)&g_xbuf[base + (size_t)8 * CL] = r1;
        }
    }
}

// ---------------- per-line fused kernel ----------------
// 1 CTA (128 threads) per line. thread == channel for sampling / conv3 / fc2.
__global__ void line_kernel(const float* __restrict__ lines,
                            const float* __restrict__ conv3_b,
                            const float* __restrict__ fc2_w,
                            const float* __restrict__ fc2_b,
                            float* __restrict__ out) {
    __shared__ int   s_off[4][32];
    __shared__ float s_w[4][32];
    __shared__ float h0s[CL][8];
    __shared__ float h1s[PL][12];   // zero-padded: data at [o][1..8]
    __shared__ float h2s[PL][8];
    __shared__ float red[4][3];

    int tid = threadIdx.x;
    int n = blockIdx.x;
    int b = n / NL;

    if (tid < 32) {
        int p = tid;
        float lam = (float)p * (1.0f / 31.0f);
        const float* lp = lines + (size_t)n * 4;
        float px = lp[0] * lam + lp[2] * (1.0f - lam) - 0.5f;
        float py = lp[1] * lam + lp[3] * (1.0f - lam) - 0.5f;
        float px0 = fminf(fmaxf(floorf(px), 0.0f), 255.0f);
        float py0 = fminf(fmaxf(floorf(py), 0.0f), 255.0f);
        float px1 = fminf(px0 + 1.0f, 255.0f);
        float py1 = fminf(py0 + 1.0f, 255.0f);
        int ix0 = (int)px0, iy0 = (int)py0, ix1 = (int)px1, iy1 = (int)py1;
        s_off[0][p] = (ix0 * HW + iy0) * CL;
        s_off[1][p] = (ix1 * HW + iy0) * CL;
        s_off[2][p] = (ix0 * HW + iy1) * CL;
        s_off[3][p] = (ix1 * HW + iy1) * CL;
        s_w[0][p] = (px1 - px) * (py1 - py);
        s_w[1][p] = (px - px0) * (py1 - py);
        s_w[2][p] = (px1 - px) * (py - py0);
        s_w[3][p] = (px - px0) * (py - py0);
    }
    // zero conv2 padding rows
    for (int i = tid; i < PL * 12; i += 128) ((float*)h1s)[i] = 0.0f;
    __syncthreads();

    // ---- bilinear sample + maxpool(4) : thread = channel ----
    const float* xb = g_xbuf + (size_t)b * NPIX * CL + tid;
    float mx[8];
#pragma unroll
    for (int p = 0; p < 32; p++) {
        float v = s_w[0][p] * __ldg(xb + s_off[0][p])
                + s_w[1][p] * __ldg(xb + s_off[1][p])
                + s_w[2][p] * __ldg(xb + s_off[2][p])
                + s_w[3][p] * __ldg(xb + s_off[3][p]);
        int g = p >> 2;
        if ((p & 3) == 0) mx[g] = v; else mx[g] = fmaxf(mx[g], v);
    }

    // ---- BN1 + ReLU ----
    {
        float a1 = g_a1[tid], b1 = g_b1c[tid];
#pragma unroll
        for (int t = 0; t < 8; t++) h0s[tid][t] = fmaxf(mx[t] * a1 + b1, 0.0f);
    }
    __syncthreads();

    int o  = tid & 63;
    int th = tid >> 6;    // 0/1
    int t0 = th * 4;

    // ---- conv1 (1x1, 128->64) + BN2 + ReLU ----
    {
        float a[4] = {0.f, 0.f, 0.f, 0.f};
#pragma unroll 8
        for (int c = 0; c < CL; c++) {
            float4 h = *(const float4*)&h0s[c][t0];
            float w = __ldg(&g_w1t[c * PL + o]);
            a[0] += w * h.x; a[1] += w * h.y; a[2] += w * h.z; a[3] += w * h.w;
        }
        float bb = g_b1f[o];
#pragma unroll
        for (int j = 0; j < 4; j++) h1s[o][1 + t0 + j] = fmaxf(a[j] + bb, 0.0f);
    }
    __syncthreads();

    // ---- conv2 (k=3 pad=1, 64->64) + BN3 + ReLU ----
    {
        float a[4] = {0.f, 0.f, 0.f, 0.f};
#pragma unroll 8
        for (int i = 0; i < PL; i++) {
            float4 hv  = *(const float4*)&h1s[i][t0];
            float2 hv2 = *(const float2*)&h1s[i][t0 + 4];
            float w0 = __ldg(&g_w2t[(i * 3 + 0) * PL + o]);
            float w1 = __ldg(&g_w2t[(i * 3 + 1) * PL + o]);
            float w2 = __ldg(&g_w2t[(i * 3 + 2) * PL + o]);
            a[0] += w0 * hv.x + w1 * hv.y  + w2 * hv.z;
            a[1] += w0 * hv.y + w1 * hv.z  + w2 * hv.w;
            a[2] += w0 * hv.z + w1 * hv.w  + w2 * hv2.x;
            a[3] += w0 * hv.w + w1 * hv2.x + w2 * hv2.y;
        }
        float bb = g_b2f[o];
#pragma unroll
        for (int j = 0; j < 4; j++) h2s[o][t0 + j] = fmaxf(a[j] + bb, 0.0f);
    }
    __syncthreads();

    // ---- conv3 (1x1, 64->128) + residual + ReLU : thread = out channel ----
    float y[8];
    {
        float a[8] = {0.f, 0.f, 0.f, 0.f, 0.f, 0.f, 0.f, 0.f};
#pragma unroll 8
        for (int i = 0; i < PL; i++) {
            float4 hlo = *(const float4*)&h2s[i][0];
            float4 hhi = *(const float4*)&h2s[i][4];
            float w = __ldg(&g_w3t[i * CL + tid]);
            a[0] += w * hlo.x; a[1] += w * hlo.y; a[2] += w * hlo.z; a[3] += w * hlo.w;
            a[4] += w * hhi.x; a[5] += w * hhi.y; a[6] += w * hhi.z; a[7] += w * hhi.w;
        }
        float cb = __ldg(&conv3_b[tid]);
#pragma unroll
        for (int t = 0; t < 8; t++) y[t] = fmaxf(mx[t] + a[t] + cb, 0.0f);
    }

    // ---- fc2: [10000,1024] @ [1024,3]^T ----
    float s[3];
    const float4* fw = (const float4*)fc2_w;
#pragma unroll
    for (int k = 0; k < 3; k++) {
        float4 wa = __ldg(&fw[k * 256 + tid * 2]);
        float4 wb = __ldg(&fw[k * 256 + tid * 2 + 1]);
        s[k] = y[0] * wa.x + y[1] * wa.y + y[2] * wa.z + y[3] * wa.w
             + y[4] * wb.x + y[5] * wb.y + y[6] * wb.z + y[7] * wb.w;
    }
#pragma unroll
    for (int k = 0; k < 3; k++) {
#pragma unroll
        for (int off = 16; off > 0; off >>= 1)
            s[k] += __shfl_down_sync(0xffffffffu, s[k], off);
    }
    int wid = tid >> 5, lane = tid & 31;
    if (lane == 0) { red[wid][0] = s[0]; red[wid][1] = s[1]; red[wid][2] = s[2]; }
    __syncthreads();
    if (tid < 3) {
        out[(size_t)n * 3 + tid] = red[0][tid] + red[1][tid] + red[2][tid] + red[3][tid]
                                 + __ldg(&fc2_b[tid]);
    }
}

// ---------------- launch ----------------
extern "C" void kernel_launch(void* const* d_in, const int* in_sizes, int n_in,
                              void* d_out, int out_size) {
    const float* feature = (const float*)d_in[0];
    const float* lines   = (const float*)d_in[1];
    const float* fc1_w   = (const float*)d_in[2];
    const float* fc1_b   = (const float*)d_in[3];
    const float* bn1_g   = (const float*)d_in[4];
    const float* bn1_b   = (const float*)d_in[5];
    const float* bn1_m   = (const float*)d_in[6];
    const float* bn1_v   = (const float*)d_in[7];
    const float* conv1_w = (const float*)d_in[8];
    const float* conv1_b = (const float*)d_in[9];
    const float* bn2_g   = (const float*)d_in[10];
    const float* bn2_b   = (const float*)d_in[11];
    const float* bn2_m   = (const float*)d_in[12];
    const float* bn2_v   = (const float*)d_in[13];
    const float* conv2_w = (const float*)d_in[14];
    const float* conv2_b = (const float*)d_in[15];
    const float* bn3_g   = (const float*)d_in[16];
    const float* bn3_b   = (const float*)d_in[17];
    const float* bn3_m   = (const float*)d_in[18];
    const float* bn3_v   = (const float*)d_in[19];
    const float* conv3_w = (const float*)d_in[20];
    const float* conv3_b = (const float*)d_in[21];
    const float* fc2_w   = (const float*)d_in[22];
    const float* fc2_b   = (const float*)d_in[23];
    float* out = (float*)d_out;

    prep_kernel<<<64, 256>>>(fc1_w, bn1_g, bn1_b, bn1_m, bn1_v,
                             conv1_w, conv1_b, bn2_g, bn2_b, bn2_m, bn2_v,
                             conv2_w, conv2_b, bn3_g, bn3_b, bn3_m, bn3_v,
                             conv3_w);
    fc1_tc_kernel<<<(NB * NPIX) / 128, 256>>>(feature, fc1_b);
    line_kernel<<<NB * NL, 128>>>(lines, conv3_b, fc2_w, fc2_b, out);
}